// round 15
// baseline (speedup 1.0000x reference)
#include <cuda_runtime.h>
#include <cuda_bf16.h>
#include <cstdint>
#include <math.h>

// Problem dims
#define BB 1024
#define DD 512
#define HH 1024
#define TT 64

#define NT 128            // 4 warps per CTA
#define GROUPS 16         // B/64 row groups
#define JPG 16            // CTAs per group (n-slices)
#define NCTA (GROUPS*JPG) // 256 -> 2 CTAs per SM

// ---------------- persistent state (all fragment-major) ----------------
__device__ float g_y[BB*DD];
__device__ float g_ks[BB*DD];
// A-operand fragments: [grp][kc][mtile(4)][512B]
__device__ char  g_xf[GROUPS*65536];    // 1MB  (32 kc)
__device__ char  g_hf[GROUPS*131072];   // 2MB  (64 kc)
// B-operand fragments: [jslice][kc][pair][512B]
__device__ char  g_W1F[1048576];        // 16 x (32 kc x 4 pairs x 512B)
__device__ char  g_W2F[1048576];        // 16 x (64 kc x 2 pairs x 512B)
__device__ unsigned g_barrier[GROUPS*32 + 32];

// ---------------- helpers ----------------
__device__ __forceinline__ void ldg_frag(uint32_t* a, const char* p) {
    asm volatile("ld.global.cg.v4.u32 {%0,%1,%2,%3}, [%4];"
                 : "=r"(a[0]), "=r"(a[1]), "=r"(a[2]), "=r"(a[3]) : "l"(p));
}
__device__ __forceinline__ void stg_v2(char* p, uint32_t v0, uint32_t v1) {
    asm volatile("st.global.v2.u32 [%0], {%1,%2};" :: "l"(p), "r"(v0), "r"(v1) : "memory");
}
__device__ __forceinline__ void mma16816(float* c, const uint32_t* a, uint32_t b0, uint32_t b1) {
    asm volatile("mma.sync.aligned.m16n8k16.row.col.f32.bf16.bf16.f32 "
                 "{%0,%1,%2,%3}, {%4,%5,%6,%7}, {%8,%9}, {%0,%1,%2,%3};"
                 : "+f"(c[0]), "+f"(c[1]), "+f"(c[2]), "+f"(c[3])
                 : "r"(a[0]), "r"(a[1]), "r"(a[2]), "r"(a[3]), "r"(b0), "r"(b1));
}

// fast tanh via MUFU ex2/rcp
__device__ __forceinline__ float fast_tanh(float x) {
    float ax = fabsf(x);
    float e, r;
    asm("ex2.approx.f32 %0, %1;" : "=f"(e) : "f"(ax * 2.8853900817779268f));
    asm("rcp.approx.f32 %0, %1;" : "=f"(r) : "f"(e + 1.0f));
    float t = fmaf(-2.0f, r, 1.0f);
    return copysignf(t, x);
}
__device__ __forceinline__ uint32_t bf2u(float a, float b) {
    __nv_bfloat162 t = __floats2bfloat162_rn(a, b);
    return *reinterpret_cast<uint32_t*>(&t);
}

// lightweight cross-CTA barrier
__device__ __forceinline__ void group_bar(unsigned* cnt, unsigned target) {
    __syncthreads();
    if (threadIdx.x == 0) {
        __threadfence();
        atomicAdd(cnt, 1u);
        while (*(volatile unsigned*)cnt < target) { __nanosleep(32); }
        __threadfence();
    }
    __syncthreads();
}

__global__ void ode_reset() {
    if (threadIdx.x < GROUPS * 32 + 32) g_barrier[threadIdx.x] = 0u;
}

// A-fragment byte offset within a group image: kc = k>>4, mt = ml>>4
__device__ __forceinline__ uint32_t afrag_off(int nmt, int ml, int k) {
    return (uint32_t)(((k >> 4) * nmt + (ml >> 4)) * 512
         + ((ml & 7) * 4 + ((k & 7) >> 1)) * 16
         + (((ml >> 3) & 1) + 2 * ((k >> 3) & 1)) * 4
         + (k & 1) * 2);
}
// B-fragment byte offset within a slice image (npairs pairs per kc)
// FIX (round 14): u must be the k-bit WITHIN the 16-k chunk -> (k>>3)&1
__device__ __forceinline__ uint32_t bfrag_off(int npairs, int n, int k) {
    int pair = n >> 4, t = (n >> 3) & 1, nn = n & 7;
    int u = (k >> 3) & 1;
    int l = nn * 4 + ((k & 7) >> 1);
    return (uint32_t)(((k >> 4) * npairs + pair) * 512 + l * 16 + (u * 2 + t) * 4 + (k & 1) * 2);
}

// ---------------- persistent fused RK4 solver ----------------
__global__ void __launch_bounds__(NT, 2)
ode_persistent(const float* __restrict__ first,
               const float* __restrict__ W1, const float* __restrict__ b1,
               const float* __restrict__ W2, const float* __restrict__ b2,
               const float* __restrict__ ts, float* __restrict__ out)
{
    __shared__ float red[2][32][32];    // [wM][acc idx][lane] K-split reduction

    const int tid  = threadIdx.x;
    const int wid  = tid >> 5, lane = tid & 31;
    const int wM   = wid & 1;          // 2 warps along M (32 rows each)
    const int wN   = wid >> 1;         // GEMM1: N-half;  GEMM2: K-half (wK)

    const int grp  = blockIdx.y;       // 0..15
    const int j    = blockIdx.x;       // 0..15
    const int cta  = grp * JPG + j;
    const int m0   = grp * 64;
    const int n1_0 = j * 64;
    const int n2_0 = j * 32;
    unsigned* cnt  = &g_barrier[grp * 32];

    // ============ init phase (partitioned across 256 CTAs) ============
    {
        const int base_i = cta * 2048;
        for (int t = tid; t < 2048; t += NT) {
            const int i = base_i + t;
            {   // W1 [D][H] -> B-fragment slices (k = d, n = h)
                int d = i / HH, h = i % HH;
                int jj = h >> 6, n = h & 63;
                uint32_t off = (uint32_t)(jj * 65536) + bfrag_off(4, n, d);
                *(__nv_bfloat16*)(g_W1F + off) = __float2bfloat16(W1[i]);
            }
            {   // W2 [H][D] -> B-fragment slices (k = h, n = d)
                int h = i / DD, d = i % DD;
                int jj = d >> 5, n = d & 31;
                uint32_t off = (uint32_t)(jj * 65536) + bfrag_off(2, n, h);
                *(__nv_bfloat16*)(g_W2F + off) = __float2bfloat16(W2[i]);
            }
            {   // state init: y, out, x fragments
                float v = first[i];
                g_y[i] = v;
                out[i] = v;
                int m = i / DD, d = i % DD;
                int gg = m >> 6, ml = m & 63;
                uint32_t off = (uint32_t)(gg * 65536) + afrag_off(4, ml, d);
                *(__nv_bfloat16*)(g_xf + off) = __float2bfloat16(v);
            }
        }
    }
    group_bar(&g_barrier[GROUPS * 32], NCTA);   // weights + x(0) visible

    const char* xg  = g_xf + grp * 65536;
    char*       hgw = g_hf + grp * 131072;
    const char* hg  = hgw;
    char*       xgw = g_xf + grp * 65536;
    const char* w1f = g_W1F + j * 65536;
    const char* w2f = g_W2F + j * 65536;

    const int rl = lane >> 2;
    const int cl = (lane & 3) * 2;
    const int lp = rl * 4 + (lane & 3);
    unsigned tgt = 0;

    for (int s = 0; s < (TT - 1) * 4; ++s) {
        const int step  = s >> 2;
        const int stage = (s & 3) + 1;

        // ================= GEMM1: h = tanh(x @ W1 + b1) =================
        // warp tile M32 x N32, serial K (kc 0..31)
        tgt += JPG;
        group_bar(cnt, tgt);

        float acc[2][4][4];
        #pragma unroll
        for (int a = 0; a < 2; ++a)
            #pragma unroll
            for (int b = 0; b < 4; ++b)
                #pragma unroll
                for (int q = 0; q < 4; ++q) acc[a][b][q] = 0.f;

        #pragma unroll 4
        for (int kc = 0; kc < 32; ++kc) {
            uint32_t af[2][4], bf[2][4];
            #pragma unroll
            for (int mi = 0; mi < 2; ++mi)
                ldg_frag(af[mi], xg + (size_t)((kc * 4 + 2 * wM + mi) * 512) + lane * 16);
            #pragma unroll
            for (int pp = 0; pp < 2; ++pp)
                ldg_frag(bf[pp], w1f + (size_t)((kc * 4 + 2 * wN + pp) * 512) + lane * 16);
            #pragma unroll
            for (int mi = 0; mi < 2; ++mi)
                #pragma unroll
                for (int pp = 0; pp < 2; ++pp) {
                    mma16816(acc[mi][2 * pp],     af[mi], bf[pp][0], bf[pp][2]);
                    mma16816(acc[mi][2 * pp + 1], af[mi], bf[pp][1], bf[pp][3]);
                }
        }

        // tanh epilogue -> h fragments, cols [n1_0 + wN*32, +32)
        #pragma unroll
        for (int mi = 0; mi < 2; ++mi) {
            const int mt = 2 * wM + mi;
            #pragma unroll
            for (int ni = 0; ni < 4; ++ni) {
                const int n = n1_0 + wN * 32 + ni * 8 + cl;
                const float bb0 = b1[n], bb1 = b1[n + 1];
                uint32_t v0 = bf2u(fast_tanh(acc[mi][ni][0] + bb0), fast_tanh(acc[mi][ni][1] + bb1));
                uint32_t v1 = bf2u(fast_tanh(acc[mi][ni][2] + bb0), fast_tanh(acc[mi][ni][3] + bb1));
                char* p = hgw + (size_t)(((n >> 4) * 4 + mt) * 512) + lp * 16 + ((n >> 3) & 1) * 8;
                stg_v2(p, v0, v1);
            }
        }

        // ================= GEMM2: k = h @ W2 + b2 ; RK4 update =================
        // warp tile M32 x N32 x K512-half (wN acts as wK)
        tgt += JPG;
        group_bar(cnt, tgt);

        float ac2[2][4][4];
        #pragma unroll
        for (int a = 0; a < 2; ++a)
            #pragma unroll
            for (int b = 0; b < 4; ++b)
                #pragma unroll
                for (int q = 0; q < 4; ++q) ac2[a][b][q] = 0.f;

        #pragma unroll 4
        for (int kk = 0; kk < 32; ++kk) {
            const int kc = wN * 32 + kk;
            uint32_t af[2][4], bf[2][4];
            #pragma unroll
            for (int mi = 0; mi < 2; ++mi)
                ldg_frag(af[mi], hg + (size_t)((kc * 4 + 2 * wM + mi) * 512) + lane * 16);
            #pragma unroll
            for (int pp = 0; pp < 2; ++pp)
                ldg_frag(bf[pp], w2f + (size_t)((kc * 2 + pp) * 512) + lane * 16);
            #pragma unroll
            for (int mi = 0; mi < 2; ++mi)
                #pragma unroll
                for (int pp = 0; pp < 2; ++pp) {
                    mma16816(ac2[mi][2 * pp],     af[mi], bf[pp][0], bf[pp][2]);
                    mma16816(ac2[mi][2 * pp + 1], af[mi], bf[pp][1], bf[pp][3]);
                }
        }

        // K-half reduction through smem
        if (wN == 1) {
            #pragma unroll
            for (int mi = 0; mi < 2; ++mi)
                #pragma unroll
                for (int b = 0; b < 4; ++b)
                    #pragma unroll
                    for (int q = 0; q < 4; ++q)
                        red[wM][mi * 16 + b * 4 + q][lane] = ac2[mi][b][q];
        }
        __syncthreads();
        if (wN == 0) {
            #pragma unroll
            for (int mi = 0; mi < 2; ++mi)
                #pragma unroll
                for (int b = 0; b < 4; ++b)
                    #pragma unroll
                    for (int q = 0; q < 4; ++q)
                        ac2[mi][b][q] += red[wM][mi * 16 + b * 4 + q][lane];

            // RK4 epilogue (warps wN==0; tile M64 x N32)
            const float dt = ts[step + 1] - ts[step];
            #pragma unroll
            for (int mi = 0; mi < 2; ++mi) {
                const int mt = 2 * wM + mi;
                #pragma unroll
                for (int ni = 0; ni < 4; ++ni) {
                    const int n = n2_0 + ni * 8 + cl;
                    const float bb0 = b2[n], bb1 = b2[n + 1];
                    uint32_t xv[2];
                    #pragma unroll
                    for (int hh = 0; hh < 2; ++hh) {
                        const int m = m0 + wM * 32 + mi * 16 + rl + hh * 8;
                        const size_t off = (size_t)m * DD + n;
                        float kq0 = ac2[mi][ni][2 * hh]     + bb0;
                        float kq1 = ac2[mi][ni][2 * hh + 1] + bb1;
                        float2 y2 = *(const float2*)(g_y + off);
                        float ks0 = 0.f, ks1 = 0.f;
                        if (stage >= 2) {
                            float2 t = *(const float2*)(g_ks + off);
                            ks0 = t.x; ks1 = t.y;
                        }
                        float x0, x1;
                        if (stage == 4) {
                            const float w = dt * (1.0f / 6.0f);
                            x0 = y2.x + w * (ks0 + kq0);
                            x1 = y2.y + w * (ks1 + kq1);
                            *(float2*)(g_y + off) = make_float2(x0, x1);
                            *(float2*)(out + (size_t)(step + 1) * (BB * DD) + off) = make_float2(x0, x1);
                        } else {
                            const float cf = (stage == 3) ? dt : 0.5f * dt;
                            const float wk = (stage == 1) ? 1.0f : 2.0f;
                            *(float2*)(g_ks + off) = make_float2(ks0 + wk * kq0, ks1 + wk * kq1);
                            x0 = y2.x + cf * kq0;
                            x1 = y2.y + cf * kq1;
                        }
                        xv[hh] = bf2u(x0, x1);
                    }
                    char* p = xgw + (size_t)(((n >> 4) * 4 + mt) * 512) + lp * 16 + ((n >> 3) & 1) * 8;
                    stg_v2(p, xv[0], xv[1]);
                }
            }
        }
        // next iteration's group_bar supplies the closing sync + release
    }
}

// ---------------- launch ----------------
extern "C" void kernel_launch(void* const* d_in, const int* in_sizes, int n_in,
                              void* d_out, int out_size)
{
    const float* first = (const float*)d_in[0];
    const float* ts    = (const float*)d_in[1];
    const float* W1    = (const float*)d_in[2];
    const float* b1    = (const float*)d_in[3];
    const float* W2    = (const float*)d_in[4];
    const float* b2    = (const float*)d_in[5];
    float* out = (float*)d_out;

    ode_reset<<<1, 576>>>();
    ode_persistent<<<dim3(JPG, GROUPS), NT>>>(first, W1, b1, W2, b2, ts, out);
}

// round 16
// speedup vs baseline: 1.7383x; 1.7383x over previous
#include <cuda_runtime.h>
#include <cuda_bf16.h>
#include <cstdint>
#include <math.h>

// Problem dims
#define BB 1024
#define DD 512
#define HH 1024
#define TT 64

#define NT 256            // 8 warps per CTA, warp = one 16-row mtile
#define GROUPS 8          // B/128 row groups
#define JPG 32            // CTAs per group (n-slices)
#define NCTA (GROUPS*JPG) // 256  -> 2 CTAs per SM

// smem: W1 slice 32KB + W2 slice 32KB + ctrl
#define OFF_W1   0
#define OFF_W2   32768
#define OFF_CTRL 65536
#define SMEM_BYTES (65536 + 64 + 1024)

// ---------------- persistent state ----------------
__device__ float g_y[BB*DD];
__device__ float g_ks[BB*DD];
// activation fragments: [grp][k16-chunk][mtile(8)][512B]  (A-fragment-major)
__device__ char  g_xf[GROUPS*131072];   // 1MB  (32 k-chunks)
__device__ char  g_hf[GROUPS*262144];   // 2MB  (64 k-chunks)
__device__ char  g_W1S[HH*DD*2];        // 32 slices x 32KB, swizzled
__device__ char  g_W2S[DD*HH*2];        // 32 slices x 32KB, swizzled
__device__ unsigned g_barrier[GROUPS*32 + 32];

// ---------------- helpers ----------------
__device__ __forceinline__ uint32_t smem_u32(const void* p) {
    uint32_t a;
    asm("{ .reg .u64 t; cvta.to.shared.u64 t, %1; cvt.u32.u64 %0, t; }" : "=r"(a) : "l"(p));
    return a;
}
__device__ __forceinline__ void bulkcp(uint32_t dst, const void* src, uint32_t bytes,
                                       uint32_t mbar) {
    asm volatile(
        "cp.async.bulk.shared::cluster.global.mbarrier::complete_tx::bytes [%0], [%1], %2, [%3];"
        :: "r"(dst), "l"(src), "r"(bytes), "r"(mbar) : "memory");
}
#define MBAR_INIT(a, c) asm volatile("mbarrier.init.shared.b64 [%0], %1;" :: "r"(a), "r"((uint32_t)(c)) : "memory")
#define MBAR_EXPECT(a, n) asm volatile("mbarrier.arrive.expect_tx.shared.b64 _, [%0], %1;" :: "r"(a), "r"((uint32_t)(n)) : "memory")
#define MBAR_WAIT(addr, ph) do {                                                        \
    uint32_t _m = (addr); uint32_t _p = (uint32_t)(ph); uint32_t _d;                    \
    asm volatile("{\n\t.reg .pred p;\n\t"                                               \
        "mbarrier.try_wait.parity.acquire.cta.shared::cta.b64 p, [%1], %2;\n\t"         \
        "selp.b32 %0,1,0,p;\n\t}" : "=r"(_d) : "r"(_m), "r"(_p) : "memory");            \
    if (!_d) {                                                                          \
        asm volatile("{\n\t.reg .pred P1;\n\t"                                          \
            "WL_%=:\n\t"                                                                \
            "mbarrier.try_wait.parity.acquire.cta.shared::cta.b64 P1, [%0], %1, 0x989680;\n\t" \
            "@P1 bra.uni WD_%=;\n\t"                                                    \
            "bra.uni WL_%=;\n\t"                                                        \
            "WD_%=:\n\t}" :: "r"(_m), "r"(_p) : "memory");                              \
    }                                                                                   \
} while (0)

__device__ __forceinline__ void ldm_x4(uint32_t& r0, uint32_t& r1, uint32_t& r2, uint32_t& r3,
                                       uint32_t addr) {
    asm volatile("ldmatrix.sync.aligned.m8n8.x4.shared.b16 {%0,%1,%2,%3}, [%4];"
                 : "=r"(r0), "=r"(r1), "=r"(r2), "=r"(r3) : "r"(addr));
}
// A fragment straight from global, L2-only (cross-CTA data -> bypass L1)
__device__ __forceinline__ void ldg_frag(uint32_t* a, const char* p) {
    asm volatile("ld.global.cg.v4.u32 {%0,%1,%2,%3}, [%4];"
                 : "=r"(a[0]), "=r"(a[1]), "=r"(a[2]), "=r"(a[3]) : "l"(p));
}
__device__ __forceinline__ void stg_v2(char* p, uint32_t v0, uint32_t v1) {
    asm volatile("st.global.v2.u32 [%0], {%1,%2};" :: "l"(p), "r"(v0), "r"(v1) : "memory");
}
__device__ __forceinline__ void mma16816(float* c, const uint32_t* a, uint32_t b0, uint32_t b1) {
    asm volatile("mma.sync.aligned.m16n8k16.row.col.f32.bf16.bf16.f32 "
                 "{%0,%1,%2,%3}, {%4,%5,%6,%7}, {%8,%9}, {%0,%1,%2,%3};"
                 : "+f"(c[0]), "+f"(c[1]), "+f"(c[2]), "+f"(c[3])
                 : "r"(a[0]), "r"(a[1]), "r"(a[2]), "r"(a[3]), "r"(b0), "r"(b1));
}

// fast tanh via MUFU ex2/rcp
__device__ __forceinline__ float fast_tanh(float x) {
    float ax = fabsf(x);
    float e, r;
    asm("ex2.approx.f32 %0, %1;" : "=f"(e) : "f"(ax * 2.8853900817779268f));
    asm("rcp.approx.f32 %0, %1;" : "=f"(r) : "f"(e + 1.0f));
    float t = fmaf(-2.0f, r, 1.0f);
    return copysignf(t, x);
}

__device__ __forceinline__ uint32_t pg_off(int m, int col_bytes) {
    return (uint32_t)((m >> 3) * 1024 + (m & 7) * 128 + (col_bytes ^ ((m & 7) << 4)));
}
__device__ __forceinline__ uint32_t bf2u(float a, float b) {
    __nv_bfloat162 t = __floats2bfloat162_rn(a, b);
    return *reinterpret_cast<uint32_t*>(&t);
}

// lightweight cross-CTA barrier
__device__ __forceinline__ void group_bar(unsigned* cnt, unsigned target) {
    __syncthreads();
    if (threadIdx.x == 0) {
        asm volatile("fence.proxy.async;" ::: "memory");
        __threadfence();
        atomicAdd(cnt, 1u);
        while (*(volatile unsigned*)cnt < target) { __nanosleep(32); }
        __threadfence();
    }
    __syncthreads();
}

__global__ void ode_reset() {
    if (threadIdx.x < GROUPS * 32 + 32) g_barrier[threadIdx.x] = 0u;
}

// ---------------- persistent fused RK4 solver ----------------
__global__ void __launch_bounds__(NT, 2)
ode_persistent(const float* __restrict__ first,
               const float* __restrict__ W1, const float* __restrict__ b1,
               const float* __restrict__ W2, const float* __restrict__ b2,
               const float* __restrict__ ts, float* __restrict__ out)
{
    extern __shared__ char smraw[];
    const uint32_t sraw = smem_u32(smraw);
    const uint32_t sb   = (sraw + 1023u) & ~1023u;
    const uint32_t w1B  = sb + OFF_W1;
    const uint32_t w2B  = sb + OFF_W2;
    const uint32_t mbW  = sb + OFF_CTRL;

    const int tid  = threadIdx.x;
    const int wid  = tid >> 5, lane = tid & 31;

    const int grp  = blockIdx.y;      // 0..7
    const int j    = blockIdx.x;      // 0..31
    const int cta  = grp * JPG + j;
    const int m0   = grp * 128;
    const int n1_0 = j * 32;          // GEMM1 N slice
    const int n2_0 = j * 16;          // GEMM2 N slice
    unsigned* cnt  = &g_barrier[grp * 32];

    if (tid == 0) MBAR_INIT(mbW, 1);

    // ============ init phase (partitioned across 256 CTAs) ============
    {
        const int base_i = cta * 2048;
        for (int t = tid; t < 2048; t += NT) {
            const int i = base_i + t;
            {   // W1 [D][H] -> slice-major swizzled (32 slices of 32 H-rows)
                int d = i / HH, h = i % HH;
                int jj = h >> 5, r = h & 31, c = d >> 6, w = d & 63;
                uint32_t off = (uint32_t)(jj * 32768 + c * 4096) + pg_off(r, w * 2);
                *(__nv_bfloat16*)(g_W1S + off) = __float2bfloat16(W1[i]);
            }
            {   // W2 [H][D] -> slice-major swizzled (32 slices of 16 D-rows)
                int h = i / DD, d = i % DD;
                int jj = d >> 4, r = d & 15, c = h >> 6, w = h & 63;
                uint32_t off = (uint32_t)(jj * 32768 + c * 2048) + pg_off(r, w * 2);
                *(__nv_bfloat16*)(g_W2S + off) = __float2bfloat16(W2[i]);
            }
            {   // state init: y, out, x in A-fragment layout
                float v = first[i];
                g_y[i] = v;
                out[i] = v;
                int m = i / DD, d = i % DD;
                int gg = m >> 7, ml = m & 127;
                uint32_t off = (uint32_t)(gg * 131072)
                             + (uint32_t)(((d >> 4) * 8 + (ml >> 4)) * 512)
                             + (uint32_t)(((ml & 7) * 4 + ((d & 7) >> 1)) * 16)
                             + (uint32_t)((((ml >> 3) & 1) + 2 * ((d >> 3) & 1)) * 4)
                             + (uint32_t)((d & 1) * 2);
                *(__nv_bfloat16*)(g_xf + off) = __float2bfloat16(v);
            }
        }
    }
    group_bar(&g_barrier[GROUPS * 32], NCTA);

    // resident weight slices (32KB + 32KB)
    if (tid == 0) {
        MBAR_EXPECT(mbW, 65536);
        bulkcp(w1B, g_W1S + (size_t)j * 32768, 32768, mbW);
        bulkcp(w2B, g_W2S + (size_t)j * 32768, 32768, mbW);
    }
    MBAR_WAIT(mbW, 0);

    const char* xg = g_xf + grp * 131072;
    const char* hg = g_hf + grp * 262144;

    const int rl = lane >> 2;
    const int cl = (lane & 3) * 2;
    const int lp = rl * 4 + (lane & 3);     // fragment lane index (bijection)
    unsigned tgt = 0;

    for (int s = 0; s < (TT - 1) * 4; ++s) {
        const int step  = s >> 2;
        const int stage = (s & 3) + 1;

        // ================= GEMM1: h = tanh(x @ W1 + b1) =================
        tgt += JPG;
        group_bar(cnt, tgt);

        float acc[4][4];
        #pragma unroll
        for (int a = 0; a < 4; ++a)
            #pragma unroll
            for (int q = 0; q < 4; ++q) acc[a][q] = 0.f;

        #pragma unroll 8
        for (int kc = 0; kc < 32; ++kc) {
            uint32_t af[4];
            ldg_frag(af, xg + (size_t)((kc * 8 + wid) * 512) + lane * 16);
            const uint32_t sW = w1B + (kc >> 2) * 4096;
            const int kb = (kc & 3) * 32 + ((lane >> 4) << 4);
            uint32_t bf[2][4];
            #pragma unroll
            for (int nj = 0; nj < 2; ++nj)
                ldm_x4(bf[nj][0], bf[nj][1], bf[nj][2], bf[nj][3],
                       sW + pg_off(nj * 16 + (lane & 15), kb));
            #pragma unroll
            for (int nj = 0; nj < 2; ++nj) {
                mma16816(acc[2 * nj],     af, bf[nj][0], bf[nj][2]);
                mma16816(acc[2 * nj + 1], af, bf[nj][1], bf[nj][3]);
            }
        }

        // tanh epilogue -> h fragments, cols [n1_0, n1_0+32)
        #pragma unroll
        for (int ni = 0; ni < 4; ++ni) {
            const int n = n1_0 + ni * 8 + cl;
            const float bb0 = b1[n], bb1 = b1[n + 1];
            uint32_t v0 = bf2u(fast_tanh(acc[ni][0] + bb0), fast_tanh(acc[ni][1] + bb1));
            uint32_t v1 = bf2u(fast_tanh(acc[ni][2] + bb0), fast_tanh(acc[ni][3] + bb1));
            char* p = (char*)hg + (size_t)(((n >> 4) * 8 + wid) * 512) + lp * 16 + ((n >> 3) & 1) * 8;
            stg_v2(p, v0, v1);
        }

        // ================= GEMM2: k = h @ W2 + b2 ; RK4 update =================
        // dual-accumulator: even kc -> ac2, odd kc -> ac2b (independent chains)
        tgt += JPG;
        group_bar(cnt, tgt);

        float ac2[2][4], ac2b[2][4];
        #pragma unroll
        for (int a = 0; a < 2; ++a)
            #pragma unroll
            for (int q = 0; q < 4; ++q) { ac2[a][q] = 0.f; ac2b[a][q] = 0.f; }

        #pragma unroll 4
        for (int kc = 0; kc < 64; kc += 2) {
            uint32_t af0[4], af1[4];
            ldg_frag(af0, hg + (size_t)(((kc)     * 8 + wid) * 512) + lane * 16);
            ldg_frag(af1, hg + (size_t)(((kc + 1) * 8 + wid) * 512) + lane * 16);

            const uint32_t sW0 = w2B + ((kc)     >> 2) * 2048;
            const uint32_t sW1 = w2B + ((kc + 1) >> 2) * 2048;
            const int kb0 = ((kc)     & 3) * 32 + ((lane >> 4) << 4);
            const int kb1 = ((kc + 1) & 3) * 32 + ((lane >> 4) << 4);
            uint32_t bf0[4], bf1[4];
            ldm_x4(bf0[0], bf0[1], bf0[2], bf0[3], sW0 + pg_off(lane & 15, kb0));
            ldm_x4(bf1[0], bf1[1], bf1[2], bf1[3], sW1 + pg_off(lane & 15, kb1));

            mma16816(ac2[0],  af0, bf0[0], bf0[2]);
            mma16816(ac2[1],  af0, bf0[1], bf0[3]);
            mma16816(ac2b[0], af1, bf1[0], bf1[2]);
            mma16816(ac2b[1], af1, bf1[1], bf1[3]);
        }
        #pragma unroll
        for (int a = 0; a < 2; ++a)
            #pragma unroll
            for (int q = 0; q < 4; ++q) ac2[a][q] += ac2b[a][q];

        // RK4 epilogue -> y/ks/out + x fragments, cols [n2_0, n2_0+16)
        const float dt = ts[step + 1] - ts[step];
        #pragma unroll
        for (int ni = 0; ni < 2; ++ni) {
            const int n = n2_0 + ni * 8 + cl;
            const float bb0 = b2[n], bb1 = b2[n + 1];
            uint32_t xv[2];
            #pragma unroll
            for (int hh = 0; hh < 2; ++hh) {
                const int m = m0 + wid * 16 + rl + hh * 8;
                const size_t off = (size_t)m * DD + n;
                float kq0 = ac2[ni][2 * hh]     + bb0;
                float kq1 = ac2[ni][2 * hh + 1] + bb1;
                float2 y2 = *(const float2*)(g_y + off);
                float ks0 = 0.f, ks1 = 0.f;
                if (stage >= 2) {
                    float2 t = *(const float2*)(g_ks + off);
                    ks0 = t.x; ks1 = t.y;
                }
                float x0, x1;
                if (stage == 4) {
                    const float w = dt * (1.0f / 6.0f);
                    x0 = y2.x + w * (ks0 + kq0);
                    x1 = y2.y + w * (ks1 + kq1);
                    *(float2*)(g_y + off) = make_float2(x0, x1);
                    *(float2*)(out + (size_t)(step + 1) * (BB * DD) + off) = make_float2(x0, x1);
                } else {
                    const float cf = (stage == 3) ? dt : 0.5f * dt;
                    const float wk = (stage == 1) ? 1.0f : 2.0f;
                    *(float2*)(g_ks + off) = make_float2(ks0 + wk * kq0, ks1 + wk * kq1);
                    x0 = y2.x + cf * kq0;
                    x1 = y2.y + cf * kq1;
                }
                xv[hh] = bf2u(x0, x1);
            }
            char* p = (char*)xg + (size_t)(((n >> 4) * 8 + wid) * 512) + lp * 16 + ((n >> 3) & 1) * 8;
            stg_v2(p, xv[0], xv[1]);
        }
        // next iteration's group_bar provides closing sync + release
    }
}

// ---------------- launch ----------------
extern "C" void kernel_launch(void* const* d_in, const int* in_sizes, int n_in,
                              void* d_out, int out_size)
{
    const float* first = (const float*)d_in[0];
    const float* ts    = (const float*)d_in[1];
    const float* W1    = (const float*)d_in[2];
    const float* b1    = (const float*)d_in[3];
    const float* W2    = (const float*)d_in[4];
    const float* b2    = (const float*)d_in[5];
    float* out = (float*)d_out;

    static bool configured = false;
    if (!configured) {
        cudaFuncSetAttribute(ode_persistent, cudaFuncAttributeMaxDynamicSharedMemorySize,
                             SMEM_BYTES);
        configured = true;
    }

    ode_reset<<<1, 288>>>();
    ode_persistent<<<dim3(JPG, GROUPS), NT, SMEM_BYTES>>>(first, W1, b1, W2, b2, ts, out);
}